// round 13
// baseline (speedup 1.0000x reference)
#include <cuda_runtime.h>
#include <cuda_bf16.h>
#include <cuda_fp16.h>
#include <cstdint>

#define NN 50000
#define EE 800000
#define HID 64

// ---------------- scratch (__device__ globals; no allocs allowed) ----------
__device__ __half g_h[NN * HID];    // gemm output (fp16) — gather source
__device__ float  g_act[NN * HID];  // layer-1 activations (fp32, feeds gemm2)
__device__ int    g_cnt[NN];        // zero at load; re-zeroed by k_fill each run
__device__ int    g_off[NN + 1];
__device__ int    g_cur[NN];
__device__ float  g_dinv[NN];
__device__ int    g_csrc[EE];
// Pre-transposed, bf16-split weights: Wt[n][k] (k contiguous)
__device__ uint16_t g_wt1h[64 * 512];
__device__ uint16_t g_wt1l[64 * 512];
__device__ uint16_t g_wt2h[64 * 64];
__device__ uint16_t g_wt2l[64 * 64];

// ---------------- helpers ---------------------------------------------------
__device__ __forceinline__ uint32_t smem_u32(const void* p) {
    uint32_t a;
    asm("{ .reg .u64 t; cvta.to.shared.u64 t, %1; cvt.u32.u64 %0, t; }"
        : "=r"(a) : "l"(p));
    return a;
}
__device__ __forceinline__ uint32_t cvt_bf16x2(float hi_elem, float lo_elem) {
    uint32_t r;
    asm("cvt.rn.bf16x2.f32 %0, %1, %2;" : "=r"(r) : "f"(hi_elem), "f"(lo_elem));
    return r;
}
__device__ __forceinline__ void split_pair(float x0, float x1,
                                           uint32_t& h, uint32_t& l) {
    h = cvt_bf16x2(x1, x0);
    float h0 = __uint_as_float(h << 16);
    float h1 = __uint_as_float(h & 0xffff0000u);
    l = cvt_bf16x2(x1 - h1, x0 - h0);
}
__device__ __forceinline__ void mma_bf16(float& d0, float& d1, float& d2, float& d3,
                                         uint32_t a0, uint32_t a1, uint32_t a2, uint32_t a3,
                                         uint32_t b0, uint32_t b1) {
    asm volatile("mma.sync.aligned.m16n8k16.row.col.f32.bf16.bf16.f32 "
                 "{%0,%1,%2,%3}, {%4,%5,%6,%7}, {%8,%9}, {%0,%1,%2,%3};"
                 : "+f"(d0), "+f"(d1), "+f"(d2), "+f"(d3)
                 : "r"(a0), "r"(a1), "r"(a2), "r"(a3), "r"(b0), "r"(b1));
}
__device__ __forceinline__ void ldsm_x4(uint32_t& r0, uint32_t& r1,
                                        uint32_t& r2, uint32_t& r3, uint32_t addr) {
    asm volatile("ldmatrix.sync.aligned.m8n8.x4.shared.b16 {%0,%1,%2,%3}, [%4];"
                 : "=r"(r0), "=r"(r1), "=r"(r2), "=r"(r3) : "r"(addr));
}

// --------- merged: histogram (blocks 0..3124) + weight prep (3125..3160) ----
__global__ void k_hist_prep(const int* __restrict__ dst,
                            const float* __restrict__ W1,
                            const float* __restrict__ W2) {
    __shared__ uint16_t th[32][33], tl[32][33];
    int b = blockIdx.x;
    if (b < EE / 256) {
        int e = b * 256 + threadIdx.x;
        atomicAdd(&g_cnt[dst[e]], 1);   // EE divisible by 256
        return;
    }
    int bb = b - EE / 256;              // 0..35
    int tx = threadIdx.x & 31, ty = threadIdx.x >> 5;
    const float* W;
    uint16_t *oh, *ol;
    int kt, ntile, Kd;
    if (bb < 32) { W = W1; oh = g_wt1h; ol = g_wt1l; kt = bb >> 1; ntile = bb & 1; Kd = 512; }
    else         { W = W2; oh = g_wt2h; ol = g_wt2l; kt = (bb - 32) >> 1; ntile = (bb - 32) & 1; Kd = 64; }
#pragma unroll
    for (int j = 0; j < 4; j++) {
        int k = kt * 32 + ty + j * 8;
        int n = ntile * 32 + tx;
        float v = W[k * 64 + n];
        uint16_t hs = __bfloat16_as_ushort(__float2bfloat16(v));
        float hf = __uint_as_float((uint32_t)hs << 16);
        uint16_t ls = __bfloat16_as_ushort(__float2bfloat16(v - hf));
        th[ty + j * 8][tx] = hs;
        tl[ty + j * 8][tx] = ls;
    }
    __syncthreads();
#pragma unroll
    for (int j = 0; j < 4; j++) {
        int n = ntile * 32 + ty + j * 8;
        int k = kt * 32 + tx;
        oh[n * Kd + k] = th[tx][ty + j * 8];
        ol[n * Kd + k] = tl[tx][ty + j * 8];
    }
}

__global__ void k_scan() {
    extern __shared__ int buf[];
    __shared__ int sm[1024];
    int t = threadIdx.x;
    for (int i = t; i < NN; i += 1024) buf[i] = g_cnt[i];
    __syncthreads();
    const int C = (NN + 1023) / 1024;
    int start = t * C, end = start + C;
    if (end > NN) end = NN;
    int sum = 0;
    for (int i = start; i < end; i++) sum += buf[i];
    sm[t] = sum;
    __syncthreads();
    for (int ofs = 1; ofs < 1024; ofs <<= 1) {
        int v = (t >= ofs) ? sm[t - ofs] : 0;
        __syncthreads();
        sm[t] += v;
        __syncthreads();
    }
    int base = sm[t] - sum;
    for (int i = start; i < end; i++) {
        int c = buf[i];
        buf[i] = base;
        base += c;
        g_dinv[i] = rsqrtf((float)(c + 1));
    }
    __syncthreads();
    for (int i = t; i < NN; i += 1024) {
        int o = buf[i];
        g_off[i] = o;
        g_cur[i] = o;
    }
    if (t == 0) g_off[NN] = EE;
}

// fill CSR; also re-zero g_cnt for the next graph replay (cnt is dead here)
__global__ void k_fill(const int* __restrict__ src, const int* __restrict__ dst) {
    int e = blockIdx.x * blockDim.x + threadIdx.x;
    if (e < NN) g_cnt[e] = 0;
    if (e >= EE) return;
    int s = src[e], d = dst[e];
    int pos = atomicAdd(&g_cur[d], 1);
    g_csrc[pos] = s;
}

// ---------------- HMMA bf16-split GEMM, 128x64 tile, warp 32x32 -------------
// OUT fp16. Block 256 thr (8 warps, 4 row-groups x 2 col-groups), K-chunks 32.
#define XST 40   // smem row stride (uint16): 80B = 5*16B -> LDSM conflict-free

__global__ __launch_bounds__(256, 2) void k_gemm(
    const float* __restrict__ X,
    const uint16_t* __restrict__ Wth, const uint16_t* __restrict__ Wtl,
    __half* __restrict__ OUT, int n, int Kdim) {
    __shared__ __align__(16) uint16_t Xh[128 * XST], Xl[128 * XST];
    __shared__ __align__(16) uint16_t Wh[64 * XST], Wl[64 * XST];
    int tid = threadIdx.x;
    int wid = tid >> 5;
    int lane = tid & 31;
    int gid = lane >> 2;
    int q = lane & 3;
    int r0 = blockIdx.x * 128;
    int rb = (wid >> 1) * 32;    // warp row base: 0,32,64,96
    int cb = (wid & 1) * 32;     // warp col base: 0 or 32

    // X staging: 128 rows x 8 float4 = 1024 float4 / 256 thr = 4 each
    int xrow = tid >> 3;          // 0..31, +32 per j
    int xkg = (tid & 7) * 4;      // k offset (floats)
    // W staging: 64 rows x 4 uint4 = 256 / 256 thr = 1 each
    int wn = tid >> 2;            // 0..63
    int wq = tid & 3;             // uint4 index within 32-k chunk

    int g8 = lane >> 3, lr = lane & 7;
    int aoff0 = (rb + lr + (g8 & 1) * 8) * XST + (g8 >> 1) * 8;
    int aoff1 = aoff0 + 16 * XST;
    int boff0 = (cb + lr + (g8 >> 1) * 8) * XST + (g8 & 1) * 8;
    int boff1 = boff0 + 16 * XST;
    uint32_t xh_b = smem_u32(Xh), xl_b = smem_u32(Xl);
    uint32_t wh_b = smem_u32(Wh), wl_b = smem_u32(Wl);

    const uint4* wh128 = (const uint4*)Wth;
    const uint4* wl128 = (const uint4*)Wtl;
    int w4stride = Kdim >> 3;     // uint4 per Wt row

    float acc[2][4][4];
#pragma unroll
    for (int t = 0; t < 2; t++)
#pragma unroll
        for (int nt = 0; nt < 4; nt++)
#pragma unroll
            for (int c = 0; c < 4; c++) acc[t][nt][c] = 0.f;

    int nch = Kdim >> 5;
    float4 px[4];
    uint4 pwh, pwl;

#pragma unroll
    for (int j = 0; j < 4; j++) {
        int gr = r0 + xrow + j * 32;
        px[j] = (gr < n) ? *(const float4*)(X + (size_t)gr * Kdim + xkg)
                         : make_float4(0.f, 0.f, 0.f, 0.f);
    }
    pwh = wh128[wn * w4stride + wq];
    pwl = wl128[wn * w4stride + wq];

    for (int ch = 0; ch < nch; ch++) {
        // stage X (bf16 hi/lo split)
#pragma unroll
        for (int j = 0; j < 4; j++) {
            int row = xrow + j * 32;
            uint32_t h01, l01, h23, l23;
            split_pair(px[j].x, px[j].y, h01, l01);
            split_pair(px[j].z, px[j].w, h23, l23);
            uint32_t* dh = (uint32_t*)&Xh[row * XST + xkg];
            uint32_t* dl = (uint32_t*)&Xl[row * XST + xkg];
            dh[0] = h01; dh[1] = h23;
            dl[0] = l01; dl[1] = l23;
        }
        // stage W (wide 16B stores)
        *(uint4*)&Wh[wn * XST + wq * 8] = pwh;
        *(uint4*)&Wl[wn * XST + wq * 8] = pwl;
        __syncthreads();

        // prefetch next chunk
        if (ch + 1 < nch) {
            int k0 = (ch + 1) << 5;
#pragma unroll
            for (int j = 0; j < 4; j++) {
                int gr = r0 + xrow + j * 32;
                px[j] = (gr < n)
                    ? *(const float4*)(X + (size_t)gr * Kdim + k0 + xkg)
                    : make_float4(0.f, 0.f, 0.f, 0.f);
            }
            pwh = wh128[wn * w4stride + (ch + 1) * 4 + wq];
            pwl = wl128[wn * w4stride + (ch + 1) * 4 + wq];
        }

#pragma unroll
        for (int s = 0; s < 2; s++) {
            uint32_t ah0[4], ah1[4], al0[4], al1[4];
            uint32_t bh0[4], bh1[4], bl0[4], bl1[4];
            ldsm_x4(ah0[0], ah0[1], ah0[2], ah0[3], xh_b + 2 * (aoff0 + s * 16));
            ldsm_x4(ah1[0], ah1[1], ah1[2], ah1[3], xh_b + 2 * (aoff1 + s * 16));
            ldsm_x4(al0[0], al0[1], al0[2], al0[3], xl_b + 2 * (aoff0 + s * 16));
            ldsm_x4(al1[0], al1[1], al1[2], al1[3], xl_b + 2 * (aoff1 + s * 16));
            ldsm_x4(bh0[0], bh0[1], bh0[2], bh0[3], wh_b + 2 * (boff0 + s * 16));
            ldsm_x4(bh1[0], bh1[1], bh1[2], bh1[3], wh_b + 2 * (boff1 + s * 16));
            ldsm_x4(bl0[0], bl0[1], bl0[2], bl0[3], wl_b + 2 * (boff0 + s * 16));
            ldsm_x4(bl1[0], bl1[1], bl1[2], bl1[3], wl_b + 2 * (boff1 + s * 16));
#pragma unroll
            for (int t = 0; t < 2; t++) {
                uint32_t *ah = t ? ah1 : ah0, *al = t ? al1 : al0;
#pragma unroll
                for (int g = 0; g < 2; g++) {
                    uint32_t *bh = g ? bh1 : bh0, *bl = g ? bl1 : bl0;
                    float* c0 = acc[t][g * 2];
                    float* c1 = acc[t][g * 2 + 1];
                    mma_bf16(c0[0], c0[1], c0[2], c0[3],
                             ah[0], ah[1], ah[2], ah[3], bh[0], bh[1]);
                    mma_bf16(c0[0], c0[1], c0[2], c0[3],
                             ah[0], ah[1], ah[2], ah[3], bl[0], bl[1]);
                    mma_bf16(c0[0], c0[1], c0[2], c0[3],
                             al[0], al[1], al[2], al[3], bh[0], bh[1]);
                    mma_bf16(c1[0], c1[1], c1[2], c1[3],
                             ah[0], ah[1], ah[2], ah[3], bh[2], bh[3]);
                    mma_bf16(c1[0], c1[1], c1[2], c1[3],
                             ah[0], ah[1], ah[2], ah[3], bl[2], bl[3]);
                    mma_bf16(c1[0], c1[1], c1[2], c1[3],
                             al[0], al[1], al[2], al[3], bh[2], bh[3]);
                }
            }
        }
        __syncthreads();
    }

#pragma unroll
    for (int t = 0; t < 2; t++) {
        int gr0 = r0 + rb + t * 16 + gid;
        int gr1 = gr0 + 8;
#pragma unroll
        for (int nt = 0; nt < 4; nt++) {
            int col = cb + nt * 8 + 2 * q;
            if (gr0 < n)
                *(__half2*)(OUT + (size_t)gr0 * HID + col) =
                    __floats2half2_rn(acc[t][nt][0], acc[t][nt][1]);
            if (gr1 < n)
                *(__half2*)(OUT + (size_t)gr1 * HID + col) =
                    __floats2half2_rn(acc[t][nt][2], acc[t][nt][3]);
        }
    }
}

// ------- gather aggregation: warp per node, half-warp per edge, fp16 rows ---
__global__ void k_agg(const __half* __restrict__ H, const float* __restrict__ bias,
                      float* __restrict__ OUT, int do_relu) {
    int node = (blockIdx.x * blockDim.x + threadIdx.x) >> 5;
    if (node >= NN) return;
    int lane = threadIdx.x & 31;
    int half = lane >> 4;          // 0 or 1
    int l = (lane & 15) * 4;       // feature offset (4 halves = 8B per lane)

    float di = g_dinv[node];
    float4 a = make_float4(0.f, 0.f, 0.f, 0.f);
    if (half == 0) {
        float sw = di * di;
        uint2 raw = *(const uint2*)(H + (size_t)node * HID + l);
        float2 v01 = __half22float2(*(const __half2*)&raw.x);
        float2 v23 = __half22float2(*(const __half2*)&raw.y);
        float4 b = *(const float4*)(bias + l);
        a.x = v01.x * sw + b.x;
        a.y = v01.y * sw + b.y;
        a.z = v23.x * sw + b.z;
        a.w = v23.y * sw + b.w;
    }

    int e = g_off[node] + half;
    int e1 = g_off[node + 1];
    for (; e + 2 < e1; e += 4) {
        int s0 = g_csrc[e];
        int s1 = g_csrc[e + 2];
        float w0 = g_dinv[s0] * di;
        float w1 = g_dinv[s1] * di;
        uint2 r0 = *(const uint2*)(H + (size_t)s0 * HID + l);
        uint2 r1 = *(const uint2*)(H + (size_t)s1 * HID + l);
        float2 p0 = __half22float2(*(const __half2*)&r0.x);
        float2 p1 = __half22float2(*(const __half2*)&r0.y);
        float2 q0 = __half22float2(*(const __half2*)&r1.x);
        float2 q1 = __half22float2(*(const __half2*)&r1.y);
        a.x += p0.x * w0; a.y += p0.y * w0; a.z += p1.x * w0; a.w += p1.y * w0;
        a.x += q0.x * w1; a.y += q0.y * w1; a.z += q1.x * w1; a.w += q1.y * w1;
    }
    for (; e < e1; e += 2) {
        int s = g_csrc[e];
        float w = g_dinv[s] * di;
        uint2 r = *(const uint2*)(H + (size_t)s * HID + l);
        float2 p0 = __half22float2(*(const __half2*)&r.x);
        float2 p1 = __half22float2(*(const __half2*)&r.y);
        a.x += p0.x * w; a.y += p0.y * w; a.z += p1.x * w; a.w += p1.y * w;
    }
    // merge halves
    a.x += __shfl_xor_sync(0xFFFFFFFFu, a.x, 16);
    a.y += __shfl_xor_sync(0xFFFFFFFFu, a.y, 16);
    a.z += __shfl_xor_sync(0xFFFFFFFFu, a.z, 16);
    a.w += __shfl_xor_sync(0xFFFFFFFFu, a.w, 16);

    if (half == 0) {
        if (do_relu) {
            a.x = fmaxf(a.x, 0.f);
            a.y = fmaxf(a.y, 0.f);
            a.z = fmaxf(a.z, 0.f);
            a.w = fmaxf(a.w, 0.f);
        }
        *(float4*)(OUT + (size_t)node * HID + l) = a;
    }
}

extern "C" void kernel_launch(void* const* d_in, const int* in_sizes, int n_in,
                              void* d_out, int out_size) {
    const float* x  = (const float*)d_in[0];
    const int*   ei = (const int*)d_in[1];   // [2, E]: src row then dst row
    const float* W1 = (const float*)d_in[2];
    const float* b1 = (const float*)d_in[3];
    const float* W2 = (const float*)d_in[4];
    const float* b2 = (const float*)d_in[5];
    float* out = (float*)d_out;
    const int* src = ei;
    const int* dst = ei + EE;

    __half* ph;
    float* pact;
    uint16_t *w1h, *w1l, *w2h, *w2l;
    cudaGetSymbolAddress((void**)&ph, g_h);
    cudaGetSymbolAddress((void**)&pact, g_act);
    cudaGetSymbolAddress((void**)&w1h, g_wt1h);
    cudaGetSymbolAddress((void**)&w1l, g_wt1l);
    cudaGetSymbolAddress((void**)&w2h, g_wt2h);
    cudaGetSymbolAddress((void**)&w2l, g_wt2l);

    cudaFuncSetAttribute(k_scan, cudaFuncAttributeMaxDynamicSharedMemorySize,
                         NN * (int)sizeof(int));

    // Serial pipeline
    k_hist_prep<<<EE / 256 + 36, 256>>>(dst, W1, W2);   // hist + weight prep
    k_scan<<<1, 1024, NN * sizeof(int)>>>();
    k_fill<<<(EE + 255) / 256, 256>>>(src, dst);        // re-zeros g_cnt

    // Layer 1
    k_gemm<<<(NN + 127) / 128, 256>>>(x, w1h, w1l, ph, NN, 512);
    k_agg<<<(NN * 32 + 255) / 256, 256>>>(ph, b1, pact, 1);
    // Layer 2
    k_gemm<<<(NN + 127) / 128, 256>>>(pact, w2h, w2l, ph, NN, HID);
    k_agg<<<(NN * 32 + 255) / 256, 256>>>(ph, b2, out, 0);
}

// round 14
// speedup vs baseline: 1.3449x; 1.3449x over previous
#include <cuda_runtime.h>
#include <cuda_bf16.h>
#include <cuda_fp16.h>
#include <cstdint>

#define NN 50000
#define EE 800000
#define HID 64

// ---------------- scratch (__device__ globals; no allocs allowed) ----------
__device__ __half g_h[NN * HID];    // gemm output (fp16) — gather source
__device__ float  g_act[NN * HID];  // layer-1 activations (fp32, feeds gemm2)
__device__ int    g_cnt[NN];        // zero at load; re-zeroed by k_fill each run
__device__ int    g_off[NN + 1];
__device__ int    g_cur[NN];
__device__ float  g_dinv[NN];
__device__ int    g_csrc[EE];
// Pre-transposed, bf16-split weights: Wt[n][k] (k contiguous)
__device__ uint16_t g_wt1h[64 * 512];
__device__ uint16_t g_wt1l[64 * 512];
__device__ uint16_t g_wt2h[64 * 64];
__device__ uint16_t g_wt2l[64 * 64];

// ---------------- helpers ---------------------------------------------------
__device__ __forceinline__ uint32_t smem_u32(const void* p) {
    uint32_t a;
    asm("{ .reg .u64 t; cvta.to.shared.u64 t, %1; cvt.u32.u64 %0, t; }"
        : "=r"(a) : "l"(p));
    return a;
}
__device__ __forceinline__ uint32_t cvt_bf16x2(float hi_elem, float lo_elem) {
    uint32_t r;
    asm("cvt.rn.bf16x2.f32 %0, %1, %2;" : "=r"(r) : "f"(hi_elem), "f"(lo_elem));
    return r;
}
__device__ __forceinline__ void split_pair(float x0, float x1,
                                           uint32_t& h, uint32_t& l) {
    h = cvt_bf16x2(x1, x0);
    float h0 = __uint_as_float(h << 16);
    float h1 = __uint_as_float(h & 0xffff0000u);
    l = cvt_bf16x2(x1 - h1, x0 - h0);
}
__device__ __forceinline__ void mma_bf16(float& d0, float& d1, float& d2, float& d3,
                                         uint32_t a0, uint32_t a1, uint32_t a2, uint32_t a3,
                                         uint32_t b0, uint32_t b1) {
    asm volatile("mma.sync.aligned.m16n8k16.row.col.f32.bf16.bf16.f32 "
                 "{%0,%1,%2,%3}, {%4,%5,%6,%7}, {%8,%9}, {%0,%1,%2,%3};"
                 : "+f"(d0), "+f"(d1), "+f"(d2), "+f"(d3)
                 : "r"(a0), "r"(a1), "r"(a2), "r"(a3), "r"(b0), "r"(b1));
}
__device__ __forceinline__ void ldsm_x4(uint32_t& r0, uint32_t& r1,
                                        uint32_t& r2, uint32_t& r3, uint32_t addr) {
    asm volatile("ldmatrix.sync.aligned.m8n8.x4.shared.b16 {%0,%1,%2,%3}, [%4];"
                 : "=r"(r0), "=r"(r1), "=r"(r2), "=r"(r3) : "r"(addr));
}

// --------- merged: histogram (blocks 0..3124) + weight prep (3125..3160) ----
__global__ void k_hist_prep(const int* __restrict__ dst,
                            const float* __restrict__ W1,
                            const float* __restrict__ W2) {
    __shared__ uint16_t th[32][33], tl[32][33];
    int b = blockIdx.x;
    if (b < EE / 256) {
        int e = b * 256 + threadIdx.x;
        atomicAdd(&g_cnt[dst[e]], 1);   // EE divisible by 256
        return;
    }
    int bb = b - EE / 256;              // 0..35
    int tx = threadIdx.x & 31, ty = threadIdx.x >> 5;
    const float* W;
    uint16_t *oh, *ol;
    int kt, ntile, Kd;
    if (bb < 32) { W = W1; oh = g_wt1h; ol = g_wt1l; kt = bb >> 1; ntile = bb & 1; Kd = 512; }
    else         { W = W2; oh = g_wt2h; ol = g_wt2l; kt = (bb - 32) >> 1; ntile = (bb - 32) & 1; Kd = 64; }
#pragma unroll
    for (int j = 0; j < 4; j++) {
        int k = kt * 32 + ty + j * 8;
        int n = ntile * 32 + tx;
        float v = W[k * 64 + n];
        uint16_t hs = __bfloat16_as_ushort(__float2bfloat16(v));
        float hf = __uint_as_float((uint32_t)hs << 16);
        uint16_t ls = __bfloat16_as_ushort(__float2bfloat16(v - hf));
        th[ty + j * 8][tx] = hs;
        tl[ty + j * 8][tx] = ls;
    }
    __syncthreads();
#pragma unroll
    for (int j = 0; j < 4; j++) {
        int n = ntile * 32 + ty + j * 8;
        int k = kt * 32 + tx;
        oh[n * Kd + k] = th[tx][ty + j * 8];
        ol[n * Kd + k] = tl[tx][ty + j * 8];
    }
}

__global__ void k_scan() {
    extern __shared__ int buf[];
    __shared__ int sm[1024];
    int t = threadIdx.x;
    for (int i = t; i < NN; i += 1024) buf[i] = g_cnt[i];
    __syncthreads();
    const int C = (NN + 1023) / 1024;
    int start = t * C, end = start + C;
    if (end > NN) end = NN;
    int sum = 0;
    for (int i = start; i < end; i++) sum += buf[i];
    sm[t] = sum;
    __syncthreads();
    for (int ofs = 1; ofs < 1024; ofs <<= 1) {
        int v = (t >= ofs) ? sm[t - ofs] : 0;
        __syncthreads();
        sm[t] += v;
        __syncthreads();
    }
    int base = sm[t] - sum;
    for (int i = start; i < end; i++) {
        int c = buf[i];
        buf[i] = base;
        base += c;
        g_dinv[i] = rsqrtf((float)(c + 1));
    }
    __syncthreads();
    for (int i = t; i < NN; i += 1024) {
        int o = buf[i];
        g_off[i] = o;
        g_cur[i] = o;
    }
    if (t == 0) g_off[NN] = EE;
}

// fill CSR; also re-zero g_cnt for the next graph replay (cnt is dead here)
__global__ void k_fill(const int* __restrict__ src, const int* __restrict__ dst) {
    int e = blockIdx.x * blockDim.x + threadIdx.x;
    if (e < NN) g_cnt[e] = 0;
    if (e >= EE) return;
    int s = src[e], d = dst[e];
    int pos = atomicAdd(&g_cur[d], 1);
    g_csrc[pos] = s;
}

// ---------------- HMMA bf16-split GEMM (ldmatrix, 64x64 tile) ---------------
// OUT fp16. Block 128 thr (4 warps), K-chunks of 32. Wide (uint4) W staging.
#define XST 40   // smem row stride (uint16): 80B = 5*16B -> LDSM conflict-free

__global__ __launch_bounds__(128, 4) void k_gemm(
    const float* __restrict__ X,
    const uint16_t* __restrict__ Wth, const uint16_t* __restrict__ Wtl,
    __half* __restrict__ OUT, int n, int Kdim) {
    __shared__ __align__(16) uint16_t Xh[64 * XST], Xl[64 * XST];
    __shared__ __align__(16) uint16_t Wh[64 * XST], Wl[64 * XST];
    int tid = threadIdx.x;
    int wid = tid >> 5;
    int lane = tid & 31;
    int gid = lane >> 2;
    int q = lane & 3;
    int r0 = blockIdx.x * 64;
    int rb = wid * 16;

    int xrow = tid >> 3;          // 0..15, +16 per j
    int xkg = (tid & 7) * 4;      // k offset (floats)
    int wn = tid >> 1;            // 0..63 (W row)
    int wq = (tid & 1) * 2;       // uint4 index within 32-k chunk (0 or 2)

    int g8 = lane >> 3, lr = lane & 7;
    int aoff = (rb + lr + (g8 & 1) * 8) * XST + (g8 >> 1) * 8;
    int boff0 = (lr + (g8 >> 1) * 8) * XST + (g8 & 1) * 8;
    uint32_t xh_b = smem_u32(Xh), xl_b = smem_u32(Xl);
    uint32_t wh_b = smem_u32(Wh), wl_b = smem_u32(Wl);

    const uint4* wh128 = (const uint4*)Wth;
    const uint4* wl128 = (const uint4*)Wtl;
    int w4stride = Kdim >> 3;     // uint4 per Wt row

    float acc[8][4];
#pragma unroll
    for (int t = 0; t < 8; t++)
#pragma unroll
        for (int c = 0; c < 4; c++) acc[t][c] = 0.f;

    int nch = Kdim >> 5;
    float4 px[4];
    uint4 pwh[2], pwl[2];

#pragma unroll
    for (int j = 0; j < 4; j++) {
        int gr = r0 + xrow + j * 16;
        px[j] = (gr < n) ? *(const float4*)(X + (size_t)gr * Kdim + xkg)
                         : make_float4(0.f, 0.f, 0.f, 0.f);
    }
#pragma unroll
    for (int j = 0; j < 2; j++) {
        pwh[j] = wh128[wn * w4stride + wq + j];
        pwl[j] = wl128[wn * w4stride + wq + j];
    }

    for (int ch = 0; ch < nch; ch++) {
        // stage X (bf16 hi/lo split)
#pragma unroll
        for (int j = 0; j < 4; j++) {
            int row = xrow + j * 16;
            uint32_t h01, l01, h23, l23;
            split_pair(px[j].x, px[j].y, h01, l01);
            split_pair(px[j].z, px[j].w, h23, l23);
            uint32_t* dh = (uint32_t*)&Xh[row * XST + xkg];
            uint32_t* dl = (uint32_t*)&Xl[row * XST + xkg];
            dh[0] = h01; dh[1] = h23;
            dl[0] = l01; dl[1] = l23;
        }
        // stage W (16B stores)
#pragma unroll
        for (int j = 0; j < 2; j++) {
            *(uint4*)&Wh[wn * XST + (wq + j) * 8] = pwh[j];
            *(uint4*)&Wl[wn * XST + (wq + j) * 8] = pwl[j];
        }
        __syncthreads();

        // prefetch next chunk
        if (ch + 1 < nch) {
            int k0 = (ch + 1) << 5;
#pragma unroll
            for (int j = 0; j < 4; j++) {
                int gr = r0 + xrow + j * 16;
                px[j] = (gr < n)
                    ? *(const float4*)(X + (size_t)gr * Kdim + k0 + xkg)
                    : make_float4(0.f, 0.f, 0.f, 0.f);
            }
#pragma unroll
            for (int j = 0; j < 2; j++) {
                pwh[j] = wh128[wn * w4stride + (ch + 1) * 4 + wq + j];
                pwl[j] = wl128[wn * w4stride + (ch + 1) * 4 + wq + j];
            }
        }

#pragma unroll
        for (int s = 0; s < 2; s++) {
            uint32_t ah[4], al[4];
            ldsm_x4(ah[0], ah[1], ah[2], ah[3], xh_b + 2 * (aoff + s * 16));
            ldsm_x4(al[0], al[1], al[2], al[3], xl_b + 2 * (aoff + s * 16));
#pragma unroll
            for (int p = 0; p < 4; p++) {
                int bo = boff0 + p * 16 * XST + s * 16;
                uint32_t bh[4], bl[4];
                ldsm_x4(bh[0], bh[1], bh[2], bh[3], wh_b + 2 * bo);
                ldsm_x4(bl[0], bl[1], bl[2], bl[3], wl_b + 2 * bo);
                int t0 = 2 * p, t1 = 2 * p + 1;
                mma_bf16(acc[t0][0], acc[t0][1], acc[t0][2], acc[t0][3],
                         ah[0], ah[1], ah[2], ah[3], bh[0], bh[1]);
                mma_bf16(acc[t0][0], acc[t0][1], acc[t0][2], acc[t0][3],
                         ah[0], ah[1], ah[2], ah[3], bl[0], bl[1]);
                mma_bf16(acc[t0][0], acc[t0][1], acc[t0][2], acc[t0][3],
                         al[0], al[1], al[2], al[3], bh[0], bh[1]);
                mma_bf16(acc[t1][0], acc[t1][1], acc[t1][2], acc[t1][3],
                         ah[0], ah[1], ah[2], ah[3], bh[2], bh[3]);
                mma_bf16(acc[t1][0], acc[t1][1], acc[t1][2], acc[t1][3],
                         ah[0], ah[1], ah[2], ah[3], bl[2], bl[3]);
                mma_bf16(acc[t1][0], acc[t1][1], acc[t1][2], acc[t1][3],
                         al[0], al[1], al[2], al[3], bh[2], bh[3]);
            }
        }
        __syncthreads();
    }

    int gr0 = r0 + rb + gid;
    int gr1 = gr0 + 8;
#pragma unroll
    for (int nt = 0; nt < 8; nt++) {
        int col = nt * 8 + 2 * q;
        if (gr0 < n)
            *(__half2*)(OUT + (size_t)gr0 * HID + col) =
                __floats2half2_rn(acc[nt][0], acc[nt][1]);
        if (gr1 < n)
            *(__half2*)(OUT + (size_t)gr1 * HID + col) =
                __floats2half2_rn(acc[nt][2], acc[nt][3]);
    }
}

// ------- gather aggregation: warp per node, half-warp per edge, fp16 rows ---
__global__ void k_agg(const __half* __restrict__ H, const float* __restrict__ bias,
                      float* __restrict__ OUT, int do_relu) {
    int node = (blockIdx.x * blockDim.x + threadIdx.x) >> 5;
    if (node >= NN) return;
    int lane = threadIdx.x & 31;
    int half = lane >> 4;          // 0 or 1
    int l = (lane & 15) * 4;       // feature offset (4 halves = 8B per lane)

    float di = g_dinv[node];
    float4 a = make_float4(0.f, 0.f, 0.f, 0.f);
    if (half == 0) {
        float sw = di * di;
        uint2 raw = *(const uint2*)(H + (size_t)node * HID + l);
        float2 v01 = __half22float2(*(const __half2*)&raw.x);
        float2 v23 = __half22float2(*(const __half2*)&raw.y);
        float4 b = *(const float4*)(bias + l);
        a.x = v01.x * sw + b.x;
        a.y = v01.y * sw + b.y;
        a.z = v23.x * sw + b.z;
        a.w = v23.y * sw + b.w;
    }

    int e = g_off[node] + half;
    int e1 = g_off[node + 1];
    for (; e + 2 < e1; e += 4) {
        int s0 = g_csrc[e];
        int s1 = g_csrc[e + 2];
        float w0 = g_dinv[s0] * di;
        float w1 = g_dinv[s1] * di;
        uint2 r0 = *(const uint2*)(H + (size_t)s0 * HID + l);
        uint2 r1 = *(const uint2*)(H + (size_t)s1 * HID + l);
        float2 p0 = __half22float2(*(const __half2*)&r0.x);
        float2 p1 = __half22float2(*(const __half2*)&r0.y);
        float2 q0 = __half22float2(*(const __half2*)&r1.x);
        float2 q1 = __half22float2(*(const __half2*)&r1.y);
        a.x += p0.x * w0; a.y += p0.y * w0; a.z += p1.x * w0; a.w += p1.y * w0;
        a.x += q0.x * w1; a.y += q0.y * w1; a.z += q1.x * w1; a.w += q1.y * w1;
    }
    for (; e < e1; e += 2) {
        int s = g_csrc[e];
        float w = g_dinv[s] * di;
        uint2 r = *(const uint2*)(H + (size_t)s * HID + l);
        float2 p0 = __half22float2(*(const __half2*)&r.x);
        float2 p1 = __half22float2(*(const __half2*)&r.y);
        a.x += p0.x * w; a.y += p0.y * w; a.z += p1.x * w; a.w += p1.y * w;
    }
    // merge halves
    a.x += __shfl_xor_sync(0xFFFFFFFFu, a.x, 16);
    a.y += __shfl_xor_sync(0xFFFFFFFFu, a.y, 16);
    a.z += __shfl_xor_sync(0xFFFFFFFFu, a.z, 16);
    a.w += __shfl_xor_sync(0xFFFFFFFFu, a.w, 16);

    if (half == 0) {
        if (do_relu) {
            a.x = fmaxf(a.x, 0.f);
            a.y = fmaxf(a.y, 0.f);
            a.z = fmaxf(a.z, 0.f);
            a.w = fmaxf(a.w, 0.f);
        }
        *(float4*)(OUT + (size_t)node * HID + l) = a;
    }
}

extern "C" void kernel_launch(void* const* d_in, const int* in_sizes, int n_in,
                              void* d_out, int out_size) {
    const float* x  = (const float*)d_in[0];
    const int*   ei = (const int*)d_in[1];   // [2, E]: src row then dst row
    const float* W1 = (const float*)d_in[2];
    const float* b1 = (const float*)d_in[3];
    const float* W2 = (const float*)d_in[4];
    const float* b2 = (const float*)d_in[5];
    float* out = (float*)d_out;
    const int* src = ei;
    const int* dst = ei + EE;

    __half* ph;
    float* pact;
    uint16_t *w1h, *w1l, *w2h, *w2l;
    cudaGetSymbolAddress((void**)&ph, g_h);
    cudaGetSymbolAddress((void**)&pact, g_act);
    cudaGetSymbolAddress((void**)&w1h, g_wt1h);
    cudaGetSymbolAddress((void**)&w1l, g_wt1l);
    cudaGetSymbolAddress((void**)&w2h, g_wt2h);
    cudaGetSymbolAddress((void**)&w2l, g_wt2l);

    cudaFuncSetAttribute(k_scan, cudaFuncAttributeMaxDynamicSharedMemorySize,
                         NN * (int)sizeof(int));

    // Serial pipeline
    k_hist_prep<<<EE / 256 + 36, 256>>>(dst, W1, W2);   // hist + weight prep
    k_scan<<<1, 1024, NN * sizeof(int)>>>();
    k_fill<<<(EE + 255) / 256, 256>>>(src, dst);        // re-zeros g_cnt

    // Layer 1
    k_gemm<<<(NN + 63) / 64, 128>>>(x, w1h, w1l, ph, NN, 512);
    k_agg<<<(NN * 32 + 255) / 256, 256>>>(ph, b1, pact, 1);
    // Layer 2
    k_gemm<<<(NN + 63) / 64, 128>>>(pact, w2h, w2l, ph, NN, HID);
    k_agg<<<(NN * 32 + 255) / 256, 256>>>(ph, b2, out, 0);
}

// round 15
// speedup vs baseline: 1.3998x; 1.0408x over previous
#include <cuda_runtime.h>
#include <cuda_bf16.h>
#include <cuda_fp16.h>
#include <cstdint>

#define NN 50000
#define EE 800000
#define HID 64

// ---------------- scratch (__device__ globals; no allocs allowed) ----------
__device__ __half g_h[NN * HID];    // gemm output (fp16) — gather source
__device__ float  g_act[NN * HID];  // layer-1 activations (fp32, feeds gemm2)
__device__ int    g_cnt[NN];        // zero at load; re-zeroed by k_fill each run
__device__ int    g_off[NN + 1];
__device__ int    g_cur[NN];
__device__ float  g_dinv[NN];
__device__ int    g_csrc[EE];
// Pre-transposed, bf16-split weights: Wt[n][k] (k contiguous)
__device__ uint16_t g_wt1h[64 * 512];
__device__ uint16_t g_wt1l[64 * 512];
__device__ uint16_t g_wt2h[64 * 64];
__device__ uint16_t g_wt2l[64 * 64];

// ---------------- helpers ---------------------------------------------------
__device__ __forceinline__ uint32_t smem_u32(const void* p) {
    uint32_t a;
    asm("{ .reg .u64 t; cvta.to.shared.u64 t, %1; cvt.u32.u64 %0, t; }"
        : "=r"(a) : "l"(p));
    return a;
}
__device__ __forceinline__ uint32_t cvt_bf16x2(float hi_elem, float lo_elem) {
    uint32_t r;
    asm("cvt.rn.bf16x2.f32 %0, %1, %2;" : "=r"(r) : "f"(hi_elem), "f"(lo_elem));
    return r;
}
__device__ __forceinline__ void split_pair(float x0, float x1,
                                           uint32_t& h, uint32_t& l) {
    h = cvt_bf16x2(x1, x0);
    float h0 = __uint_as_float(h << 16);
    float h1 = __uint_as_float(h & 0xffff0000u);
    l = cvt_bf16x2(x1 - h1, x0 - h0);
}
__device__ __forceinline__ void mma_bf16(float& d0, float& d1, float& d2, float& d3,
                                         uint32_t a0, uint32_t a1, uint32_t a2, uint32_t a3,
                                         uint32_t b0, uint32_t b1) {
    asm volatile("mma.sync.aligned.m16n8k16.row.col.f32.bf16.bf16.f32 "
                 "{%0,%1,%2,%3}, {%4,%5,%6,%7}, {%8,%9}, {%0,%1,%2,%3};"
                 : "+f"(d0), "+f"(d1), "+f"(d2), "+f"(d3)
                 : "r"(a0), "r"(a1), "r"(a2), "r"(a3), "r"(b0), "r"(b1));
}
__device__ __forceinline__ void ldsm_x4(uint32_t& r0, uint32_t& r1,
                                        uint32_t& r2, uint32_t& r3, uint32_t addr) {
    asm volatile("ldmatrix.sync.aligned.m8n8.x4.shared.b16 {%0,%1,%2,%3}, [%4];"
                 : "=r"(r0), "=r"(r1), "=r"(r2), "=r"(r3) : "r"(addr));
}

// --------- merged: histogram (blocks 0..3124) + weight prep (3125..3160) ----
__global__ void k_hist_prep(const int* __restrict__ dst,
                            const float* __restrict__ W1,
                            const float* __restrict__ W2) {
    __shared__ uint16_t th[32][33], tl[32][33];
    int b = blockIdx.x;
    if (b < EE / 256) {
        int e = b * 256 + threadIdx.x;
        atomicAdd(&g_cnt[dst[e]], 1);   // EE divisible by 256
        return;
    }
    int bb = b - EE / 256;              // 0..35
    int tx = threadIdx.x & 31, ty = threadIdx.x >> 5;
    const float* W;
    uint16_t *oh, *ol;
    int kt, ntile, Kd;
    if (bb < 32) { W = W1; oh = g_wt1h; ol = g_wt1l; kt = bb >> 1; ntile = bb & 1; Kd = 512; }
    else         { W = W2; oh = g_wt2h; ol = g_wt2l; kt = (bb - 32) >> 1; ntile = (bb - 32) & 1; Kd = 64; }
#pragma unroll
    for (int j = 0; j < 4; j++) {
        int k = kt * 32 + ty + j * 8;
        int n = ntile * 32 + tx;
        float v = W[k * 64 + n];
        uint16_t hs = __bfloat16_as_ushort(__float2bfloat16(v));
        float hf = __uint_as_float((uint32_t)hs << 16);
        uint16_t ls = __bfloat16_as_ushort(__float2bfloat16(v - hf));
        th[ty + j * 8][tx] = hs;
        tl[ty + j * 8][tx] = ls;
    }
    __syncthreads();
#pragma unroll
    for (int j = 0; j < 4; j++) {
        int n = ntile * 32 + ty + j * 8;
        int k = kt * 32 + tx;
        oh[n * Kd + k] = th[tx][ty + j * 8];
        ol[n * Kd + k] = tl[tx][ty + j * 8];
    }
}

__global__ void k_scan() {
    extern __shared__ int buf[];
    __shared__ int sm[1024];
    int t = threadIdx.x;
    for (int i = t; i < NN; i += 1024) buf[i] = g_cnt[i];
    __syncthreads();
    const int C = (NN + 1023) / 1024;
    int start = t * C, end = start + C;
    if (end > NN) end = NN;
    int sum = 0;
    for (int i = start; i < end; i++) sum += buf[i];
    sm[t] = sum;
    __syncthreads();
    for (int ofs = 1; ofs < 1024; ofs <<= 1) {
        int v = (t >= ofs) ? sm[t - ofs] : 0;
        __syncthreads();
        sm[t] += v;
        __syncthreads();
    }
    int base = sm[t] - sum;
    for (int i = start; i < end; i++) {
        int c = buf[i];
        buf[i] = base;
        base += c;
        g_dinv[i] = rsqrtf((float)(c + 1));
    }
    __syncthreads();
    for (int i = t; i < NN; i += 1024) {
        int o = buf[i];
        g_off[i] = o;
        g_cur[i] = o;
    }
    if (t == 0) g_off[NN] = EE;
}

// fill CSR; also re-zero g_cnt for the next graph replay (cnt is dead here)
__global__ void k_fill(const int* __restrict__ src, const int* __restrict__ dst) {
    int e = blockIdx.x * blockDim.x + threadIdx.x;
    if (e < NN) g_cnt[e] = 0;
    if (e >= EE) return;
    int s = src[e], d = dst[e];
    int pos = atomicAdd(&g_cur[d], 1);
    g_csrc[pos] = s;
}

// ------- HMMA bf16-split GEMM: 64x64 block tile, 2x2 grid of 32x32 warp tiles
// OUT fp16. Block 128 thr (4 warps), K-chunks of 32. Scalar W staging (R12).
#define XST 40   // smem row stride (uint16): 80B = 5*16B -> LDSM conflict-free

__global__ __launch_bounds__(128, 4) void k_gemm(
    const float* __restrict__ X,
    const uint16_t* __restrict__ Wth, const uint16_t* __restrict__ Wtl,
    __half* __restrict__ OUT, int n, int Kdim) {
    __shared__ __align__(16) uint16_t Xh[64 * XST], Xl[64 * XST];
    __shared__ __align__(16) uint16_t Wh[64 * XST], Wl[64 * XST];
    int tid = threadIdx.x;
    int wid = tid >> 5;
    int lane = tid & 31;
    int gid = lane >> 2;
    int q = lane & 3;
    int r0 = blockIdx.x * 64;
    int rb = (wid >> 1) * 32;    // warp row base: 0 or 32
    int cb = (wid & 1) * 32;     // warp col base: 0 or 32

    int xrow = tid >> 3;          // 0..15, +16 per j
    int xkg = (tid & 7) * 4;      // k offset (floats)
    int wn = tid >> 4;            // 0..7, +8 per j
    int wkg = tid & 15;           // uint32 index within 32-k row

    int g8 = lane >> 3, lr = lane & 7;
    int aoff0 = (rb + lr + (g8 & 1) * 8) * XST + (g8 >> 1) * 8;
    int aoff1 = aoff0 + 16 * XST;
    int boff0 = (cb + lr + (g8 >> 1) * 8) * XST + (g8 & 1) * 8;
    int boff1 = boff0 + 16 * XST;
    uint32_t xh_b = smem_u32(Xh), xl_b = smem_u32(Xl);
    uint32_t wh_b = smem_u32(Wh), wl_b = smem_u32(Wl);

    const uint32_t* wh32 = (const uint32_t*)Wth;
    const uint32_t* wl32 = (const uint32_t*)Wtl;
    int wstride = Kdim >> 1;

    float acc[2][4][4];
#pragma unroll
    for (int t = 0; t < 2; t++)
#pragma unroll
        for (int nt = 0; nt < 4; nt++)
#pragma unroll
            for (int c = 0; c < 4; c++) acc[t][nt][c] = 0.f;

    int nch = Kdim >> 5;
    float4 px[4];
    uint32_t pwh[8], pwl[8];

#pragma unroll
    for (int j = 0; j < 4; j++) {
        int gr = r0 + xrow + j * 16;
        px[j] = (gr < n) ? *(const float4*)(X + (size_t)gr * Kdim + xkg)
                         : make_float4(0.f, 0.f, 0.f, 0.f);
    }
#pragma unroll
    for (int j = 0; j < 8; j++) {
        int nn = wn + j * 8;
        pwh[j] = wh32[nn * wstride + wkg];
        pwl[j] = wl32[nn * wstride + wkg];
    }

    for (int ch = 0; ch < nch; ch++) {
#pragma unroll
        for (int j = 0; j < 4; j++) {
            int row = xrow + j * 16;
            uint32_t h01, l01, h23, l23;
            split_pair(px[j].x, px[j].y, h01, l01);
            split_pair(px[j].z, px[j].w, h23, l23);
            uint32_t* dh = (uint32_t*)&Xh[row * XST + xkg];
            uint32_t* dl = (uint32_t*)&Xl[row * XST + xkg];
            dh[0] = h01; dh[1] = h23;
            dl[0] = l01; dl[1] = l23;
        }
#pragma unroll
        for (int j = 0; j < 8; j++) {
            int nn = wn + j * 8;
            *(uint32_t*)&Wh[nn * XST + wkg * 2] = pwh[j];
            *(uint32_t*)&Wl[nn * XST + wkg * 2] = pwl[j];
        }
        __syncthreads();

        if (ch + 1 < nch) {
            int k0 = (ch + 1) << 5;
#pragma unroll
            for (int j = 0; j < 4; j++) {
                int gr = r0 + xrow + j * 16;
                px[j] = (gr < n)
                    ? *(const float4*)(X + (size_t)gr * Kdim + k0 + xkg)
                    : make_float4(0.f, 0.f, 0.f, 0.f);
            }
#pragma unroll
            for (int j = 0; j < 8; j++) {
                int nn = wn + j * 8;
                pwh[j] = wh32[nn * wstride + (k0 >> 1) + wkg];
                pwl[j] = wl32[nn * wstride + (k0 >> 1) + wkg];
            }
        }

#pragma unroll
        for (int s = 0; s < 2; s++) {
            uint32_t ah0[4], ah1[4], al0[4], al1[4];
            uint32_t bh0[4], bh1[4], bl0[4], bl1[4];
            ldsm_x4(ah0[0], ah0[1], ah0[2], ah0[3], xh_b + 2 * (aoff0 + s * 16));
            ldsm_x4(ah1[0], ah1[1], ah1[2], ah1[3], xh_b + 2 * (aoff1 + s * 16));
            ldsm_x4(al0[0], al0[1], al0[2], al0[3], xl_b + 2 * (aoff0 + s * 16));
            ldsm_x4(al1[0], al1[1], al1[2], al1[3], xl_b + 2 * (aoff1 + s * 16));
            ldsm_x4(bh0[0], bh0[1], bh0[2], bh0[3], wh_b + 2 * (boff0 + s * 16));
            ldsm_x4(bh1[0], bh1[1], bh1[2], bh1[3], wh_b + 2 * (boff1 + s * 16));
            ldsm_x4(bl0[0], bl0[1], bl0[2], bl0[3], wl_b + 2 * (boff0 + s * 16));
            ldsm_x4(bl1[0], bl1[1], bl1[2], bl1[3], wl_b + 2 * (boff1 + s * 16));
#pragma unroll
            for (int t = 0; t < 2; t++) {
                uint32_t *ah = t ? ah1 : ah0, *al = t ? al1 : al0;
#pragma unroll
                for (int g = 0; g < 2; g++) {
                    uint32_t *bh = g ? bh1 : bh0, *bl = g ? bl1 : bl0;
                    float* c0 = acc[t][g * 2];
                    float* c1 = acc[t][g * 2 + 1];
                    mma_bf16(c0[0], c0[1], c0[2], c0[3],
                             ah[0], ah[1], ah[2], ah[3], bh[0], bh[1]);
                    mma_bf16(c0[0], c0[1], c0[2], c0[3],
                             ah[0], ah[1], ah[2], ah[3], bl[0], bl[1]);
                    mma_bf16(c0[0], c0[1], c0[2], c0[3],
                             al[0], al[1], al[2], al[3], bh[0], bh[1]);
                    mma_bf16(c1[0], c1[1], c1[2], c1[3],
                             ah[0], ah[1], ah[2], ah[3], bh[2], bh[3]);
                    mma_bf16(c1[0], c1[1], c1[2], c1[3],
                             ah[0], ah[1], ah[2], ah[3], bl[2], bl[3]);
                    mma_bf16(c1[0], c1[1], c1[2], c1[3],
                             al[0], al[1], al[2], al[3], bh[2], bh[3]);
                }
            }
        }
        __syncthreads();
    }

#pragma unroll
    for (int t = 0; t < 2; t++) {
        int gr0 = r0 + rb + t * 16 + gid;
        int gr1 = gr0 + 8;
#pragma unroll
        for (int nt = 0; nt < 4; nt++) {
            int col = cb + nt * 8 + 2 * q;
            if (gr0 < n)
                *(__half2*)(OUT + (size_t)gr0 * HID + col) =
                    __floats2half2_rn(acc[t][nt][0], acc[t][nt][1]);
            if (gr1 < n)
                *(__half2*)(OUT + (size_t)gr1 * HID + col) =
                    __floats2half2_rn(acc[t][nt][2], acc[t][nt][3]);
        }
    }
}

// ------- gather aggregation: warp per node, half-warp per edge, fp16 rows ---
__global__ void k_agg(const __half* __restrict__ H, const float* __restrict__ bias,
                      float* __restrict__ OUT, int do_relu) {
    int node = (blockIdx.x * blockDim.x + threadIdx.x) >> 5;
    if (node >= NN) return;
    int lane = threadIdx.x & 31;
    int half = lane >> 4;          // 0 or 1
    int l = (lane & 15) * 4;       // feature offset (4 halves = 8B per lane)

    float di = g_dinv[node];
    float4 a = make_float4(0.f, 0.f, 0.f, 0.f);
    if (half == 0) {
        float sw = di * di;
        uint2 raw = *(const uint2*)(H + (size_t)node * HID + l);
        float2 v01 = __half22float2(*(const __half2*)&raw.x);
        float2 v23 = __half22float2(*(const __half2*)&raw.y);
        float4 b = *(const float4*)(bias + l);
        a.x = v01.x * sw + b.x;
        a.y = v01.y * sw + b.y;
        a.z = v23.x * sw + b.z;
        a.w = v23.y * sw + b.w;
    }

    int e = g_off[node] + half;
    int e1 = g_off[node + 1];
    for (; e + 2 < e1; e += 4) {
        int s0 = g_csrc[e];
        int s1 = g_csrc[e + 2];
        float w0 = g_dinv[s0] * di;
        float w1 = g_dinv[s1] * di;
        uint2 r0 = *(const uint2*)(H + (size_t)s0 * HID + l);
        uint2 r1 = *(const uint2*)(H + (size_t)s1 * HID + l);
        float2 p0 = __half22float2(*(const __half2*)&r0.x);
        float2 p1 = __half22float2(*(const __half2*)&r0.y);
        float2 q0 = __half22float2(*(const __half2*)&r1.x);
        float2 q1 = __half22float2(*(const __half2*)&r1.y);
        a.x += p0.x * w0; a.y += p0.y * w0; a.z += p1.x * w0; a.w += p1.y * w0;
        a.x += q0.x * w1; a.y += q0.y * w1; a.z += q1.x * w1; a.w += q1.y * w1;
    }
    for (; e < e1; e += 2) {
        int s = g_csrc[e];
        float w = g_dinv[s] * di;
        uint2 r = *(const uint2*)(H + (size_t)s * HID + l);
        float2 p0 = __half22float2(*(const __half2*)&r.x);
        float2 p1 = __half22float2(*(const __half2*)&r.y);
        a.x += p0.x * w; a.y += p0.y * w; a.z += p1.x * w; a.w += p1.y * w;
    }
    // merge halves
    a.x += __shfl_xor_sync(0xFFFFFFFFu, a.x, 16);
    a.y += __shfl_xor_sync(0xFFFFFFFFu, a.y, 16);
    a.z += __shfl_xor_sync(0xFFFFFFFFu, a.z, 16);
    a.w += __shfl_xor_sync(0xFFFFFFFFu, a.w, 16);

    if (half == 0) {
        if (do_relu) {
            a.x = fmaxf(a.x, 0.f);
            a.y = fmaxf(a.y, 0.f);
            a.z = fmaxf(a.z, 0.f);
            a.w = fmaxf(a.w, 0.f);
        }
        *(float4*)(OUT + (size_t)node * HID + l) = a;
    }
}

extern "C" void kernel_launch(void* const* d_in, const int* in_sizes, int n_in,
                              void* d_out, int out_size) {
    const float* x  = (const float*)d_in[0];
    const int*   ei = (const int*)d_in[1];   // [2, E]: src row then dst row
    const float* W1 = (const float*)d_in[2];
    const float* b1 = (const float*)d_in[3];
    const float* W2 = (const float*)d_in[4];
    const float* b2 = (const float*)d_in[5];
    float* out = (float*)d_out;
    const int* src = ei;
    const int* dst = ei + EE;

    __half* ph;
    float* pact;
    uint16_t *w1h, *w1l, *w2h, *w2l;
    cudaGetSymbolAddress((void**)&ph, g_h);
    cudaGetSymbolAddress((void**)&pact, g_act);
    cudaGetSymbolAddress((void**)&w1h, g_wt1h);
    cudaGetSymbolAddress((void**)&w1l, g_wt1l);
    cudaGetSymbolAddress((void**)&w2h, g_wt2h);
    cudaGetSymbolAddress((void**)&w2l, g_wt2l);

    cudaFuncSetAttribute(k_scan, cudaFuncAttributeMaxDynamicSharedMemorySize,
                         NN * (int)sizeof(int));

    // Serial pipeline
    k_hist_prep<<<EE / 256 + 36, 256>>>(dst, W1, W2);   // hist + weight prep
    k_scan<<<1, 1024, NN * sizeof(int)>>>();
    k_fill<<<(EE + 255) / 256, 256>>>(src, dst);        // re-zeros g_cnt

    // Layer 1
    k_gemm<<<(NN + 63) / 64, 128>>>(x, w1h, w1l, ph, NN, 512);
    k_agg<<<(NN * 32 + 255) / 256, 256>>>(ph, b1, pact, 1);
    // Layer 2
    k_gemm<<<(NN + 63) / 64, 128>>>(pact, w2h, w2l, ph, NN, HID);
    k_agg<<<(NN * 32 + 255) / 256, 256>>>(ph, b2, out, 0);
}